// round 11
// baseline (speedup 1.0000x reference)
#include <cuda_runtime.h>

#define IMG    512
#define OUTD   502
#define NIMG   96
#define TILE_W 86
#define VCOLS  96
#define TILE_H 16
#define STRIPH 64
#define CHUNKS 4
#define GBX    6
#define GBY    8
#define NBLK   (GBX * GBY * NIMG)   // 4608
#define SROW   104                   // phase-2 buffer stride (bank-conflict-free, verified)
#define G      11                    // phase-2 outputs per thread

// Gaussian(sigma=1.5, K=11) normalized weights
#define W0 0.00102839f
#define W1 0.00759864f
#define W2 0.03600077f
#define W3 0.10936070f
#define W4 0.21300553f
#define W5 0.26601172f

typedef unsigned long long u64;

// ---- packed f32x2 helpers (sm_100+) ----
#define PACK2(out, lo, hi) asm("mov.b64 %0, {%1, %2};" : "=l"(out) : "f"(lo), "f"(hi))
#define UNPACK2(lo, hi, in) asm("mov.b64 {%0, %1}, %2;" : "=f"(lo), "=f"(hi) : "l"(in))
#define FMA2(d, a, b, c) asm("fma.rn.f32x2 %0, %1, %2, %3;" : "=l"(d) : "l"(a), "l"(b), "l"(c))
#define MUL2(d, a, b)    asm("mul.rn.f32x2 %0, %1, %2;" : "=l"(d) : "l"(a), "l"(b))

__device__ int      g_flags[2] = {0, 0};
__device__ unsigned g_count    = 0u;
__device__ float    g_partials[NBLK];

// any(img1 > 128), any(img1 < -0.5)
__global__ void k_flags(const float4* __restrict__ x, int n4) {
    bool f1 = false, f2 = false;
    for (int i = blockIdx.x * blockDim.x + threadIdx.x; i < n4; i += gridDim.x * blockDim.x) {
        float4 v = x[i];
        f1 |= (v.x > 128.0f) | (v.y > 128.0f) | (v.z > 128.0f) | (v.w > 128.0f);
        f2 |= (v.x < -0.5f) | (v.y < -0.5f) | (v.z < -0.5f) | (v.w < -0.5f);
    }
    unsigned m1 = __ballot_sync(0xffffffffu, f1);
    unsigned m2 = __ballot_sync(0xffffffffu, f2);
    if ((threadIdx.x & 31) == 0) {
        if (m1) atomicOr(&g_flags[0], 1);
        if (m2) atomicOr(&g_flags[1], 1);
    }
}

__global__ __launch_bounds__(128, 5)
void k_ssim(const float* __restrict__ img1, const float* __restrict__ img2,
            float* __restrict__ out) {
    __shared__ u64   s01[TILE_H][SROW];    // packed (vconv a, vconv b), completed rows
    __shared__ u64   sq [TILE_H][SROW];    // packed (vconv a^2+b^2, vconv a*b)
    __shared__ u64   c01[10][VCOLS];       // carry: partial vconv of next 10 output rows
    __shared__ u64   cq [10][VCOLS];
    __shared__ float warpsum[4];
    __shared__ int   s_last;
    __shared__ double red[4];

    u64 w2[6];
    {
        const float wv[6] = {W0, W1, W2, W3, W4, W5};
#pragma unroll
        for (int k = 0; k < 6; k++) PACK2(w2[k], wv[k], wv[k]);
    }
#define WIDX(k) ((k) < 6 ? (k) : 10 - (k))

    const int tid = threadIdx.x;
    const int bx = blockIdx.x, by = blockIdx.y, z = blockIdx.z;
    const float* p1 = img1 + (size_t)z * IMG * IMG;
    const float* p2 = img2 + (size_t)z * IMG * IMG;
    const int sy = by * STRIPH;            // strip output row base

    const int gx = bx * TILE_W + tid;
    const bool colok = (tid < VCOLS) && (gx < IMG);

    // ---------------- Warmup: inputs sy..sy+9 -> carry slots 0..9 -------------------------
    if (tid < VCOLS) {
        u64 a01[10], aq[10];
#pragma unroll
        for (int i = 0; i < 10; i++) {
            const int yin = sy + i;        // sy <= 448, so yin <= 457 < 512 always
            float a = 0.0f, b = 0.0f;
            if (colok) {
                a = p1[yin * IMG + gx];
                b = p2[yin * IMG + gx];
            }
            const float ab   = a * b;
            const float aabb = fmaf(a, a, b * b);
            u64 vab, vq;
            PACK2(vab, a, b);
            PACK2(vq, aabb, ab);
            MUL2(a01[i], vab, w2[0]);      // output i, first tap (k=0, W0): fresh start
            MUL2(aq[i],  vq,  w2[0]);
#pragma unroll
            for (int k = 1; k <= 10; k++) {
                if (k <= i) {
                    FMA2(a01[i - k], vab, w2[WIDX(k)], a01[i - k]);
                    FMA2(aq[i - k],  vq,  w2[WIDX(k)], aq[i - k]);
                }
            }
        }
#pragma unroll
        for (int k = 0; k < 10; k++) { c01[k][tid] = a01[k]; cq[k][tid] = aq[k]; }
    }
    // no sync needed: carry is same-thread

    // ---------------- SSIM constants ----------------
    const float maxv = g_flags[0] ? 255.0f : 1.0f;
    const float minv = g_flags[1] ? -1.0f : 0.0f;
    const float L  = maxv - minv;
    const float C1 = (0.01f * L) * (0.01f * L);
    const float C2 = (0.03f * L) * (0.03f * L);

    const int y  = tid >> 3;      // 0..15 phase-2 output row
    const int cg = tid & 7;       // 0..7  column group
    const int xs = cg * G;        // local out cols xs..xs+10
    const int xlim = min(TILE_W, OUTD - bx * TILE_W);

    float lsum = 0.0f;

    // ---------------- Chunk loop: 4 chunks of 16 output rows ------------------------------
#pragma unroll 1
    for (int c = 0; c < CHUNKS; c++) {
        // ---- Phase 1: 16 input rows; carried rolling 16-slot accumulators ----
        if (tid < VCOLS) {
            u64 acc01[16], accq[16];
#pragma unroll
            for (int k = 0; k < 10; k++) { acc01[k] = c01[k][tid]; accq[k] = cq[k][tid]; }

            const int yb = sy + c * 16 + 10;
#pragma unroll
            for (int p = 0; p < 16; p++) {
                const int yin = yb + p;
                float a = 0.0f, b = 0.0f;
                if (colok && yin < IMG) {
                    a = p1[yin * IMG + gx];
                    b = p2[yin * IMG + gx];
                }
                const float ab   = a * b;
                const float aabb = fmaf(a, a, b * b);
                u64 vab, vq;
                PACK2(vab, a, b);
                PACK2(vq, aabb, ab);
                const int mn = (10 + p) & 15;   // newest output slot: fresh start (k=0)
                MUL2(acc01[mn], vab, w2[0]);
                MUL2(accq[mn],  vq,  w2[0]);
#pragma unroll
                for (int k = 1; k <= 10; k++) {
                    const int m = (10 + p - k) & 15;
                    FMA2(acc01[m], vab, w2[WIDX(k)], acc01[m]);
                    FMA2(accq[m],  vq,  w2[WIDX(k)], accq[m]);
                }
                // output (strip-rel) c*16+p completes now (slot p): store to phase-2 buffer
                s01[p][tid] = acc01[p];
                sq [p][tid] = accq[p];
            }

            // carry out: outputs c*16+16 .. c*16+25 live in slots 0..9
#pragma unroll
            for (int k = 0; k < 10; k++) { c01[k][tid] = acc01[k]; cq[k][tid] = accq[k]; }
        }
        __syncthreads();

        // ---- Phase 2: horizontal 11-tap conv + map ----
        u64 o01[G], oq[G];
#pragma unroll
        for (int s = 0; s < G; s++) { o01[s] = 0ull; oq[s] = 0ull; }

        {
            const u64* r01 = &s01[y][xs];
#pragma unroll
            for (int i = 0; i < 21; i++) {
                const u64 v = r01[i];
#pragma unroll
                for (int s = 0; s < G; s++) {
                    const int k = i - s;
                    if (k >= 0 && k < 11) FMA2(o01[s], v, w2[WIDX(k)], o01[s]);
                }
            }
        }
        {
            const u64* rq = &sq[y][xs];
#pragma unroll
            for (int i = 0; i < 21; i++) {
                const u64 v = rq[i];
#pragma unroll
                for (int s = 0; s < G; s++) {
                    const int k = i - s;
                    if (k >= 0 && k < 11) FMA2(oq[s], v, w2[WIDX(k)], oq[s]);
                }
            }
        }

        const int gy = sy + c * 16 + y;
        if (gy < OUTD) {
#pragma unroll
            for (int s = 0; s < G; s++) {
                const int x = xs + s;
                if (x < xlim) {
                    float mu1, mu2, spp, sab;
                    UNPACK2(mu1, mu2, o01[s]);
                    UNPACK2(spp, sab, oq[s]);
                    const float mu1s = mu1 * mu1, mu2s = mu2 * mu2, mu12 = mu1 * mu2;
                    const float sigsum = spp - mu1s - mu2s;
                    const float sig12  = sab - mu12;
                    const float num = (2.0f * mu12 + C1) * (2.0f * sig12 + C2);
                    const float den = (mu1s + mu2s + C1) * (sigsum + C2);
                    lsum += __fdividef(num, den);
                }
            }
        }
        __syncthreads();   // before next chunk overwrites s01/sq
    }

    // ---------------- block reduction ----------------
#pragma unroll
    for (int off = 16; off > 0; off >>= 1)
        lsum += __shfl_down_sync(0xffffffffu, lsum, off);

    if ((tid & 31) == 0) warpsum[tid >> 5] = lsum;
    __syncthreads();

    const int bid = bx + GBX * (by + GBY * z);
    if (tid == 0) {
        g_partials[bid] = warpsum[0] + warpsum[1] + warpsum[2] + warpsum[3];
        __threadfence();
        unsigned v = atomicAdd(&g_count, 1u);
        s_last = (v == NBLK - 1) ? 1 : 0;
    }
    __syncthreads();

    // ---------------- last block: final reduction + state reset ----------------
    if (s_last) {
        double s = 0.0;
        const int per = NBLK / 128;  // 36
#pragma unroll 4
        for (int i = 0; i < per; i++)
            s += (double)__ldcg(&g_partials[tid * per + i]);
#pragma unroll
        for (int off = 16; off > 0; off >>= 1)
            s += __shfl_down_sync(0xffffffffu, s, off);
        if ((tid & 31) == 0) red[tid >> 5] = s;
        __syncthreads();
        if (tid == 0) {
            const double cnt = (double)NIMG * OUTD * OUTD;
            out[0] = (float)(1.0 - (red[0] + red[1] + red[2] + red[3]) / cnt);
            g_flags[0] = 0;
            g_flags[1] = 0;
            g_count    = 0u;
        }
    }
}

extern "C" void kernel_launch(void* const* d_in, const int* in_sizes, int n_in,
                              void* d_out, int out_size) {
    const float* img1 = (const float*)d_in[0];
    const float* img2 = (const float*)d_in[1];
    float* out = (float*)d_out;

    k_flags<<<2048, 256>>>((const float4*)img1, (IMG * IMG * NIMG) / 4);
    dim3 grid(GBX, GBY, NIMG);
    k_ssim<<<grid, 128>>>(img1, img2, out);
}

// round 12
// speedup vs baseline: 1.0441x; 1.0441x over previous
#include <cuda_runtime.h>

#define IMG    512
#define OUTD   502
#define NIMG   96
#define TILE_W 86
#define VCOLS  96
#define TILE_H 16
#define GBX    6
#define GBY    32
#define NBLK   (GBX * GBY * NIMG)   // 18432
#define SROW   104                   // bank-conflict-free (u64 planes; verified mod 16)
#define G      11                    // phase-2 outputs per thread

// Gaussian(sigma=1.5, K=11) normalized weights
#define W0 0.00102839f
#define W1 0.00759864f
#define W2 0.03600077f
#define W3 0.10936070f
#define W4 0.21300553f
#define W5 0.26601172f

typedef unsigned long long u64;

// ---- packed f32x2 helpers (sm_100+) ----
#define PACK2(out, lo, hi) asm("mov.b64 %0, {%1, %2};" : "=l"(out) : "f"(lo), "f"(hi))
#define UNPACK2(lo, hi, in) asm("mov.b64 {%0, %1}, %2;" : "=f"(lo), "=f"(hi) : "l"(in))
#define FMA2(d, a, b, c) asm("fma.rn.f32x2 %0, %1, %2, %3;" : "=l"(d) : "l"(a), "l"(b), "l"(c))

__device__ int      g_flags[2] = {0, 0};
__device__ unsigned g_count    = 0u;
__device__ float    g_partials[NBLK];

// any(img1 > 128), any(img1 < -0.5)
__global__ void k_flags(const float4* __restrict__ x, int n4) {
    bool f1 = false, f2 = false;
    for (int i = blockIdx.x * blockDim.x + threadIdx.x; i < n4; i += gridDim.x * blockDim.x) {
        float4 v = x[i];
        f1 |= (v.x > 128.0f) | (v.y > 128.0f) | (v.z > 128.0f) | (v.w > 128.0f);
        f2 |= (v.x < -0.5f) | (v.y < -0.5f) | (v.z < -0.5f) | (v.w < -0.5f);
    }
    unsigned m1 = __ballot_sync(0xffffffffu, f1);
    unsigned m2 = __ballot_sync(0xffffffffu, f2);
    if ((threadIdx.x & 31) == 0) {
        if (m1) atomicOr(&g_flags[0], 1);
        if (m2) atomicOr(&g_flags[1], 1);
    }
}

__global__ __launch_bounds__(128, 7)
void k_ssim(const float* __restrict__ img1, const float* __restrict__ img2,
            float* __restrict__ out) {
    __shared__ u64   s01[TILE_H][SROW];   // packed (vconv a, vconv b)
    __shared__ u64   sq [TILE_H][SROW];   // packed (vconv a^2+b^2, vconv a*b)
    __shared__ float warpsum[4];
    __shared__ int   s_last;
    __shared__ double red[4];

    u64 w2[6];
    {
        const float wv[6] = {W0, W1, W2, W3, W4, W5};
#pragma unroll
        for (int k = 0; k < 6; k++) PACK2(w2[k], wv[k], wv[k]);
    }
#define WIDX(k) ((k) < 6 ? (k) : 10 - (k))

    const int tid = threadIdx.x;
    const int bx = blockIdx.x, by = blockIdx.y, z = blockIdx.z;
    const float* p1 = img1 + (size_t)z * IMG * IMG;
    const float* p2 = img2 + (size_t)z * IMG * IMG;
    const int ybase = by * TILE_H;

    // ------ Phase 1: vertical 11-tap conv, ROLLING 11-slot accumulators (44 regs live) ------
    if (tid < VCOLS) {
        const int gx = bx * TILE_W + tid;
        const bool colok = (gx < IMG);

        u64 acc01[11], accq[11];
#pragma unroll
        for (int m = 0; m < 11; m++) { acc01[m] = 0ull; accq[m] = 0ull; }

#pragma unroll
        for (int j = 0; j < TILE_H + 10; j++) {
            const int yin = ybase + j;
            float a = 0.0f, b = 0.0f;
            if (colok && yin < IMG) {
                a = p1[yin * IMG + gx];
                b = p2[yin * IMG + gx];
            }
            const float ab   = a * b;
            const float aabb = fmaf(a, a, b * b);
            u64 vab, vq;
            PACK2(vab, a, b);
            PACK2(vq, aabb, ab);

            // input row j feeds output rows r in [j-10, j] clipped to [0, TILE_H-1]
#pragma unroll
            for (int r = 0; r < TILE_H; r++) {
                const int k = j - r;
                if (k >= 0 && k < 11) {
                    const int m = r % 11;          // static after unroll
                    FMA2(acc01[m], vab, w2[WIDX(k)], acc01[m]);
                    FMA2(accq[m],  vq,  w2[WIDX(k)], accq[m]);
                }
            }

            // output row j-10 is complete: store and recycle its slot
            if (j >= 10) {
                const int r = j - 10;
                const int m = r % 11;
                s01[r][tid] = acc01[m];
                sq [r][tid] = accq[m];
                if (r + 11 < TILE_H) {             // slot reused by row r+11
                    acc01[m] = 0ull;
                    accq[m]  = 0ull;
                }
            }
        }
    }
    __syncthreads();

    // ---------------- Phase 2: horizontal 11-tap conv, 11 outputs per thread --------------
    const int y  = tid >> 3;      // 0..15 output row
    const int cg = tid & 7;       // 0..7  column group
    const int xs = cg * G;        // local out cols xs..xs+10 (reads to xs+20 <= 97 < SROW)

    u64 o01[G], oq[G];
#pragma unroll
    for (int s = 0; s < G; s++) { o01[s] = 0ull; oq[s] = 0ull; }

    {
        const u64* r01 = &s01[y][xs];
#pragma unroll
        for (int i = 0; i < 21; i++) {
            const u64 v = r01[i];
#pragma unroll
            for (int s = 0; s < G; s++) {
                const int k = i - s;
                if (k >= 0 && k < 11) FMA2(o01[s], v, w2[WIDX(k)], o01[s]);
            }
        }
    }
    {
        const u64* rq = &sq[y][xs];
#pragma unroll
        for (int i = 0; i < 21; i++) {
            const u64 v = rq[i];
#pragma unroll
            for (int s = 0; s < G; s++) {
                const int k = i - s;
                if (k >= 0 && k < 11) FMA2(oq[s], v, w2[WIDX(k)], oq[s]);
            }
        }
    }

    // ---------------- SSIM map + block-local sum ----------------
    const float maxv = g_flags[0] ? 255.0f : 1.0f;
    const float minv = g_flags[1] ? -1.0f : 0.0f;
    const float L  = maxv - minv;
    const float C1 = (0.01f * L) * (0.01f * L);
    const float C2 = (0.03f * L) * (0.03f * L);

    const int gy   = ybase + y;
    const int xlim = min(TILE_W, OUTD - bx * TILE_W);

    float lsum = 0.0f;
    if (gy < OUTD) {
#pragma unroll
        for (int s = 0; s < G; s++) {
            const int x = xs + s;
            if (x < xlim) {
                float mu1, mu2, spp, sab;
                UNPACK2(mu1, mu2, o01[s]);
                UNPACK2(spp, sab, oq[s]);
                const float mu1s = mu1 * mu1, mu2s = mu2 * mu2, mu12 = mu1 * mu2;
                const float sigsum = spp - mu1s - mu2s;   // sigma1_sq + sigma2_sq
                const float sig12  = sab - mu12;          // sigma12
                const float num = (2.0f * mu12 + C1) * (2.0f * sig12 + C2);
                const float den = (mu1s + mu2s + C1) * (sigsum + C2);
                lsum += __fdividef(num, den);
            }
        }
    }

#pragma unroll
    for (int off = 16; off > 0; off >>= 1)
        lsum += __shfl_down_sync(0xffffffffu, lsum, off);

    if ((tid & 31) == 0) warpsum[tid >> 5] = lsum;
    __syncthreads();

    const int bid = bx + GBX * (by + GBY * z);
    if (tid == 0) {
        g_partials[bid] = warpsum[0] + warpsum[1] + warpsum[2] + warpsum[3];
        __threadfence();
        unsigned v = atomicAdd(&g_count, 1u);
        s_last = (v == NBLK - 1) ? 1 : 0;
    }
    __syncthreads();

    // ---------------- last block: final reduction + state reset ----------------
    if (s_last) {
        double s = 0.0;
        const int per = NBLK / 128;  // 144
#pragma unroll 4
        for (int i = 0; i < per; i++)
            s += (double)__ldcg(&g_partials[tid * per + i]);
#pragma unroll
        for (int off = 16; off > 0; off >>= 1)
            s += __shfl_down_sync(0xffffffffu, s, off);
        if ((tid & 31) == 0) red[tid >> 5] = s;
        __syncthreads();
        if (tid == 0) {
            const double cnt = (double)NIMG * OUTD * OUTD;
            out[0] = (float)(1.0 - (red[0] + red[1] + red[2] + red[3]) / cnt);
            g_flags[0] = 0;
            g_flags[1] = 0;
            g_count    = 0u;
        }
    }
}

extern "C" void kernel_launch(void* const* d_in, const int* in_sizes, int n_in,
                              void* d_out, int out_size) {
    const float* img1 = (const float*)d_in[0];
    const float* img2 = (const float*)d_in[1];
    float* out = (float*)d_out;

    k_flags<<<2048, 256>>>((const float4*)img1, (IMG * IMG * NIMG) / 4);
    dim3 grid(GBX, GBY, NIMG);
    k_ssim<<<grid, 128>>>(img1, img2, out);
}

// round 13
// speedup vs baseline: 1.1015x; 1.0549x over previous
#include <cuda_runtime.h>

#define IMG    512
#define OUTD   502
#define NIMG   96
#define TILE_W 86
#define VCOLS  96
#define TILE_H 16
#define GBX    6
#define GBY    32
#define NBLK   (GBX * GBY * NIMG)   // 18432
#define SROW   104                   // bank-conflict-free (u64 planes; verified mod 16)
#define G      11                    // phase-2 outputs per thread

// k_flags exact partition
#define FB     3072
#define FT     256
#define FITER  8                     // 3072*256*8 = 6291456 = 96*512*512/4

// Gaussian(sigma=1.5, K=11) normalized weights
#define W0 0.00102839f
#define W1 0.00759864f
#define W2 0.03600077f
#define W3 0.10936070f
#define W4 0.21300553f
#define W5 0.26601172f

typedef unsigned long long u64;

// ---- packed f32x2 helpers (sm_100+) ----
#define PACK2(out, lo, hi) asm("mov.b64 %0, {%1, %2};" : "=l"(out) : "f"(lo), "f"(hi))
#define UNPACK2(lo, hi, in) asm("mov.b64 {%0, %1}, %2;" : "=f"(lo), "=f"(hi) : "l"(in))
#define FMA2(d, a, b, c) asm("fma.rn.f32x2 %0, %1, %2, %3;" : "=l"(d) : "l"(a), "l"(b), "l"(c))
#define MUL2(d, a, b)    asm("mul.rn.f32x2 %0, %1, %2;" : "=l"(d) : "l"(a), "l"(b))

__device__ int      g_flags[2] = {0, 0};
__device__ unsigned g_count    = 0u;
__device__ float    g_partials[NBLK];

// any(img1 > 128), any(img1 < -0.5); exact partition, 8 independent loads/thread
__global__ __launch_bounds__(FT)
void k_flags(const float4* __restrict__ x) {
    const int base = blockIdx.x * FT + threadIdx.x;
    bool f1 = false, f2 = false;
#pragma unroll
    for (int i = 0; i < FITER; i++) {
        float4 v = x[base + i * (FB * FT)];
        f1 |= (v.x > 128.0f) | (v.y > 128.0f) | (v.z > 128.0f) | (v.w > 128.0f);
        f2 |= (v.x < -0.5f) | (v.y < -0.5f) | (v.z < -0.5f) | (v.w < -0.5f);
    }
    unsigned m1 = __ballot_sync(0xffffffffu, f1);
    unsigned m2 = __ballot_sync(0xffffffffu, f2);
    if ((threadIdx.x & 31) == 0) {
        if (m1) atomicOr(&g_flags[0], 1);
        if (m2) atomicOr(&g_flags[1], 1);
    }
}

// phase-1 vertical conv body; ROWGUARD selects per-row bounds checking
template <bool ROWGUARD>
__device__ __forceinline__ void vconv(const float* __restrict__ p1,
                                      const float* __restrict__ p2,
                                      int ybase, int gx, bool colok,
                                      const u64* w2,
                                      u64 (*s01)[SROW], u64 (*sq)[SROW], int tid) {
    u64 acc01[11], accq[11];

#pragma unroll
    for (int j = 0; j < TILE_H + 10; j++) {
        const int yin = ybase + j;
        float a = 0.0f, b = 0.0f;
        if (colok && (!ROWGUARD || yin < IMG)) {
            a = p1[yin * IMG + gx];
            b = p2[yin * IMG + gx];
        }
        const float ab   = a * b;
        const float aabb = fmaf(a, a, b * b);
        u64 vab, vq;
        PACK2(vab, a, b);
        PACK2(vq, aabb, ab);

        // input row j feeds output rows r in [j-10, j] ∩ [0, TILE_H-1]
#pragma unroll
        for (int r = 0; r < TILE_H; r++) {
            const int k = j - r;
            if (k > 0 && k < 11) {
                const int m = r % 11;                  // static after unroll
                const u64 w = w2[(k) < 6 ? (k) : 10 - (k)];
                FMA2(acc01[m], vab, w, acc01[m]);
                FMA2(accq[m],  vq,  w, accq[m]);
            } else if (k == 0) {                       // first tap: overwrite (no zero-init)
                const int m = r % 11;
                MUL2(acc01[m], vab, w2[0]);
                MUL2(accq[m],  vq,  w2[0]);
            }
        }

        if (j >= 10) {                                 // output row j-10 complete
            const int r = j - 10;
            const int m = r % 11;
            s01[r][tid] = acc01[m];
            sq [r][tid] = accq[m];
        }
    }
}

__global__ __launch_bounds__(128, 7)
void k_ssim(const float* __restrict__ img1, const float* __restrict__ img2,
            float* __restrict__ out) {
    __shared__ u64   s01[TILE_H][SROW];   // packed (vconv a, vconv b)
    __shared__ u64   sq [TILE_H][SROW];   // packed (vconv a^2+b^2, vconv a*b)
    __shared__ float warpsum[4];
    __shared__ int   s_last;
    __shared__ double red[4];

    u64 w2[6];
    {
        const float wv[6] = {W0, W1, W2, W3, W4, W5};
#pragma unroll
        for (int k = 0; k < 6; k++) PACK2(w2[k], wv[k], wv[k]);
    }
#define WIDX(k) ((k) < 6 ? (k) : 10 - (k))

    const int tid = threadIdx.x;
    const int bx = blockIdx.x, by = blockIdx.y, z = blockIdx.z;
    const float* p1 = img1 + (size_t)z * IMG * IMG;
    const float* p2 = img2 + (size_t)z * IMG * IMG;
    const int ybase = by * TILE_H;

    // ---------------- Phase 1: vertical conv (warps 0-2; warp 3 skips) --------------------
    if (tid < VCOLS) {
        const int gx = bx * TILE_W + tid;
        const bool colok = (gx < IMG);
        if (ybase + TILE_H + 10 <= IMG) {              // uniform: true for by < 31
            vconv<false>(p1, p2, ybase, gx, colok, w2, s01, sq, tid);
        } else {
            vconv<true>(p1, p2, ybase, gx, colok, w2, s01, sq, tid);
        }
    }
    __syncthreads();

    // ---------------- Phase 2: horizontal 11-tap conv, 11 outputs per thread --------------
    const int y  = tid >> 3;      // 0..15 output row
    const int cg = tid & 7;       // 0..7  column group
    const int xs = cg * G;        // local out cols xs..xs+10 (reads to xs+20 <= 97 < SROW)

    u64 o01[G], oq[G];
#pragma unroll
    for (int s = 0; s < G; s++) { o01[s] = 0ull; oq[s] = 0ull; }

    {
        const u64* r01 = &s01[y][xs];
#pragma unroll
        for (int i = 0; i < 21; i++) {
            const u64 v = r01[i];
#pragma unroll
            for (int s = 0; s < G; s++) {
                const int k = i - s;
                if (k >= 0 && k < 11) FMA2(o01[s], v, w2[WIDX(k)], o01[s]);
            }
        }
    }
    {
        const u64* rq = &sq[y][xs];
#pragma unroll
        for (int i = 0; i < 21; i++) {
            const u64 v = rq[i];
#pragma unroll
            for (int s = 0; s < G; s++) {
                const int k = i - s;
                if (k >= 0 && k < 11) FMA2(oq[s], v, w2[WIDX(k)], oq[s]);
            }
        }
    }

    // ---------------- SSIM map + block-local sum ----------------
    const float maxv = g_flags[0] ? 255.0f : 1.0f;
    const float minv = g_flags[1] ? -1.0f : 0.0f;
    const float L  = maxv - minv;
    const float C1 = (0.01f * L) * (0.01f * L);
    const float C2 = (0.03f * L) * (0.03f * L);

    const int gy   = ybase + y;
    const int xlim = min(TILE_W, OUTD - bx * TILE_W);

    float lsum = 0.0f;
    if (gy < OUTD) {
#pragma unroll
        for (int s = 0; s < G; s++) {
            const int x = xs + s;
            if (x < xlim) {
                float mu1, mu2, spp, sab;
                UNPACK2(mu1, mu2, o01[s]);
                UNPACK2(spp, sab, oq[s]);
                const float mu1s = mu1 * mu1, mu2s = mu2 * mu2, mu12 = mu1 * mu2;
                const float sigsum = spp - mu1s - mu2s;   // sigma1_sq + sigma2_sq
                const float sig12  = sab - mu12;          // sigma12
                const float num = (2.0f * mu12 + C1) * (2.0f * sig12 + C2);
                const float den = (mu1s + mu2s + C1) * (sigsum + C2);
                lsum += __fdividef(num, den);
            }
        }
    }

#pragma unroll
    for (int off = 16; off > 0; off >>= 1)
        lsum += __shfl_down_sync(0xffffffffu, lsum, off);

    if ((tid & 31) == 0) warpsum[tid >> 5] = lsum;
    __syncthreads();

    const int bid = bx + GBX * (by + GBY * z);
    if (tid == 0) {
        g_partials[bid] = warpsum[0] + warpsum[1] + warpsum[2] + warpsum[3];
        __threadfence();
        unsigned v = atomicAdd(&g_count, 1u);
        s_last = (v == NBLK - 1) ? 1 : 0;
    }
    __syncthreads();

    // ---------------- last block: final reduction + state reset ----------------
    if (s_last) {
        double s = 0.0;
        const int per = NBLK / 128;  // 144
#pragma unroll 4
        for (int i = 0; i < per; i++)
            s += (double)__ldcg(&g_partials[tid * per + i]);
#pragma unroll
        for (int off = 16; off > 0; off >>= 1)
            s += __shfl_down_sync(0xffffffffu, s, off);
        if ((tid & 31) == 0) red[tid >> 5] = s;
        __syncthreads();
        if (tid == 0) {
            const double cnt = (double)NIMG * OUTD * OUTD;
            out[0] = (float)(1.0 - (red[0] + red[1] + red[2] + red[3]) / cnt);
            g_flags[0] = 0;
            g_flags[1] = 0;
            g_count    = 0u;
        }
    }
}

extern "C" void kernel_launch(void* const* d_in, const int* in_sizes, int n_in,
                              void* d_out, int out_size) {
    const float* img1 = (const float*)d_in[0];
    const float* img2 = (const float*)d_in[1];
    float* out = (float*)d_out;

    k_flags<<<FB, FT>>>((const float4*)img1);
    dim3 grid(GBX, GBY, NIMG);
    k_ssim<<<grid, 128>>>(img1, img2, out);
}